// round 16
// baseline (speedup 1.0000x reference)
#include <cuda_runtime.h>
#include <cuda_fp16.h>
#include <math_constants.h>
#include <cstdint>
#include <cstddef>

#define B_ 8
#define L_ 1024
#define C_ 1024
#define H_ 16
#define D_ 64
#define MAXSC 4.6051701859880914f  // log(100)

// ---------------------------------------------------------------------------
// Scratch (bss, no runtime allocation)
// ---------------------------------------------------------------------------
__device__ __half g_xhi[B_ * L_ * C_];
__device__ __half g_wqh[3 * C_ * C_];
__device__ __half g_wph[C_ * C_];

__device__ __half g_qh[B_ * H_ * L_ * D_];
__device__ __half g_kh[B_ * H_ * L_ * D_];
__device__ __half g_vh[B_ * H_ * L_ * D_];

__device__ __half g_aoh[B_ * L_ * C_];

// ---------------------------------------------------------------------------
// Helpers
// ---------------------------------------------------------------------------
__device__ __forceinline__ uint32_t smem_u32(const void* p) {
    uint32_t a;
    asm("{ .reg .u64 t; cvta.to.shared.u64 t, %1; cvt.u32.u64 %0, t; }"
        : "=r"(a) : "l"(p));
    return a;
}

__device__ __forceinline__ void mma16816(float* c, const uint32_t* a,
                                         uint32_t b0, uint32_t b1)
{
    asm volatile(
        "mma.sync.aligned.m16n8k16.row.col.f32.f16.f16.f32 "
        "{%0,%1,%2,%3}, {%4,%5,%6,%7}, {%8,%9}, {%0,%1,%2,%3};"
        : "+f"(c[0]), "+f"(c[1]), "+f"(c[2]), "+f"(c[3])
        : "r"(a[0]), "r"(a[1]), "r"(a[2]), "r"(a[3]), "r"(b0), "r"(b1));
}

__device__ __forceinline__ void ldsm_x4(uint32_t* r, uint32_t addr) {
    asm volatile("ldmatrix.sync.aligned.m8n8.x4.shared.b16 {%0,%1,%2,%3}, [%4];"
        : "=r"(r[0]), "=r"(r[1]), "=r"(r[2]), "=r"(r[3]) : "r"(addr));
}
__device__ __forceinline__ void ldsm_x4_t(uint32_t* r, uint32_t addr) {
    asm volatile("ldmatrix.sync.aligned.m8n8.x4.trans.shared.b16 {%0,%1,%2,%3}, [%4];"
        : "=r"(r[0]), "=r"(r[1]), "=r"(r[2]), "=r"(r[3]) : "r"(addr));
}

__device__ __forceinline__ uint32_t pack_f16(float a, float b) {
    __half2 t = __floats2half2_rn(a, b);
    return *(uint32_t*)&t;
}

__device__ __forceinline__ void cp_async16(uint32_t saddr, const void* gptr) {
    asm volatile("cp.async.cg.shared.global [%0], [%1], 16;"
        :: "r"(saddr), "l"(gptr) : "memory");
}
__device__ __forceinline__ void cp_commit() {
    asm volatile("cp.async.commit_group;" ::: "memory");
}
template <int N>
__device__ __forceinline__ void cp_wait() {
    asm volatile("cp.async.wait_group %0;" :: "n"(N) : "memory");
}

// ---------------------------------------------------------------------------
// Merged fp32->fp16 conversion for x, W_qkv, W_proj (one launch)
// ---------------------------------------------------------------------------
#define N4X  (B_ * L_ * C_ / 4)
#define N4WQ (3 * C_ * C_ / 4)
#define N4WP (C_ * C_ / 4)
__global__ __launch_bounds__(256) void conv_all_kernel(
    const float* __restrict__ x, const float* __restrict__ wq,
    const float* __restrict__ wp,
    __half* __restrict__ xhi, __half* __restrict__ wqh,
    __half* __restrict__ wph)
{
    int i = blockIdx.x * blockDim.x + threadIdx.x;
    const float* src;
    __half* dst;
    int j;
    if (i < N4X) { src = x; dst = xhi; j = i; }
    else if (i < N4X + N4WQ) { src = wq; dst = wqh; j = i - N4X; }
    else if (i < N4X + N4WQ + N4WP) { src = wp; dst = wph; j = i - N4X - N4WQ; }
    else return;
    float4 v = ((const float4*)src)[j];
    ((__half2*)dst)[2 * j]     = __floats2half2_rn(v.x, v.y);
    ((__half2*)dst)[2 * j + 1] = __floats2half2_rn(v.z, v.w);
}

// ---------------------------------------------------------------------------
// QKV GEMM: pure fp16 1-term.  K-chunk 64, 3-stage cp.async.
// Fused epilogue: l2norm + scale + RoPE -> g_qh/kh/vh.
// ---------------------------------------------------------------------------
#define PSTAGE 32768
__global__ __launch_bounds__(256, 2) void gemm_qkv_kernel(
    const __half* __restrict__ Ahi, const __half* __restrict__ Bhi,
    const float* __restrict__ bias_q, const float* __restrict__ bias_v,
    const float* __restrict__ freqs, const float* __restrict__ sml,
    int N, int K)
{
    extern __shared__ __align__(16) char smc[];
    uint32_t sb = smem_u32(smc);
    int t = threadIdx.x;
    int wid = t >> 5, lane = t & 31;
    int wm = wid & 3, wn = wid >> 2;
    int m0 = blockIdx.y * 128, n0 = blockIdx.x * 128;

    float acc[2][8][4];
    #pragma unroll
    for (int i = 0; i < 2; i++)
        #pragma unroll
        for (int j = 0; j < 8; j++)
            #pragma unroll
            for (int u = 0; u < 4; u++) acc[i][j][u] = 0.f;

    int qrow = lane >> 2;
    int qk   = (lane & 3) * 2;
    int g = lane >> 3, r8 = lane & 7;
    int arow = (g & 1) * 8 + r8;
    uint32_t xv = (uint32_t)(r8 << 4);
    uint32_t ccol = (uint32_t)((g >> 1) * 16);
    const int niter = K >> 6;

    auto issue = [&](int it, int s) {
        int k0 = it << 6;
        uint32_t stb = sb + (uint32_t)s * PSTAGE;
        #pragma unroll
        for (int i = 0; i < 4; i++) {
            int c = t + i * 256;
            int row = c >> 3, cg = c & 7;
            uint32_t off = (uint32_t)(row * 128 + cg * 16);
            uint32_t swo = off ^ ((off >> 3) & 0x70);
            cp_async16(stb + swo,
                       Ahi + (size_t)(m0 + row) * K + k0 + cg * 8);
            cp_async16(stb + 16384 + swo,
                       Bhi + (size_t)(n0 + row) * K + k0 + cg * 8);
        }
        cp_commit();
    };

    issue(0, 0);
    issue(1, 1);
    int s = 0;
    for (int it = 0; it < niter; it++) {
        if (it + 1 < niter) cp_wait<1>(); else cp_wait<0>();
        __syncthreads();
        if (it + 2 < niter) {
            int s2 = s + 2; if (s2 >= 3) s2 -= 3;
            issue(it + 2, s2);
        }

        uint32_t sA = sb + (uint32_t)s * PSTAGE;
        uint32_t sB = sA + 16384;

        #pragma unroll
        for (int ks = 0; ks < 4; ks++) {
            uint32_t cc = ((uint32_t)(ks * 32) + ccol) ^ xv;
            uint32_t afh[2][4];
            #pragma unroll
            for (int mf = 0; mf < 2; mf++) {
                uint32_t rb = (uint32_t)((wm * 32 + mf * 16 + arow) * 128);
                ldsm_x4(afh[mf], sA + rb + cc);
            }
            #pragma unroll
            for (int nfp = 0; nfp < 4; nfp++) {
                uint32_t rb = (uint32_t)((wn * 64 + nfp * 16 + arow) * 128);
                uint32_t b4[4];
                ldsm_x4(b4, sB + rb + cc);
                #pragma unroll
                for (int mf = 0; mf < 2; mf++) {
                    mma16816(acc[mf][2 * nfp],     afh[mf], b4[0], b4[2]);
                    mma16816(acc[mf][2 * nfp + 1], afh[mf], b4[1], b4[3]);
                }
            }
        }
        if (++s >= 3) s -= 3;
    }

    // fused l2norm + scale + RoPE epilogue.  region 0=q, 1=k, 2=v.
    int region = blockIdx.x >> 3;
    int head   = ((blockIdx.x & 7) << 1) + wn;
    float smul = (region == 0) ? __expf(fminf(sml[head], MAXSC)) : 1.f;
    const float2* fr2 = (const float2*)freqs;

    #pragma unroll
    for (int mf = 0; mf < 2; mf++) {
        int r0 = m0 + wm * 32 + mf * 16 + qrow;
        int bb = r0 >> 10;
        int lA = r0 & 1023, lB = lA + 8;
        size_t baseA = ((size_t)(bb * H_ + head) * L_ + lA) * D_;
        size_t baseB = baseA + 8 * D_;

        float sA = 0.f, sB = 0.f;
        #pragma unroll
        for (int nf = 0; nf < 8; nf++) {
            int d = nf * 8 + qk;
            float bv0 = 0.f, bv1 = 0.f;
            if (region == 0) { bv0 = bias_q[head * D_ + d]; bv1 = bias_q[head * D_ + d + 1]; }
            if (region == 2) { bv0 = bias_v[head * D_ + d]; bv1 = bias_v[head * D_ + d + 1]; }
            acc[mf][nf][0] += bv0; acc[mf][nf][1] += bv1;
            acc[mf][nf][2] += bv0; acc[mf][nf][3] += bv1;
            if (region < 2) {
                sA += acc[mf][nf][0] * acc[mf][nf][0] + acc[mf][nf][1] * acc[mf][nf][1];
                sB += acc[mf][nf][2] * acc[mf][nf][2] + acc[mf][nf][3] * acc[mf][nf][3];
            }
        }

        if (region < 2) {
            sA += __shfl_xor_sync(0xffffffffu, sA, 1);
            sA += __shfl_xor_sync(0xffffffffu, sA, 2);
            sB += __shfl_xor_sync(0xffffffffu, sB, 1);
            sB += __shfl_xor_sync(0xffffffffu, sB, 2);
            float invA = smul / fmaxf(sqrtf(sA), 1e-12f);
            float invB = smul / fmaxf(sqrtf(sB), 1e-12f);

            __half* dst = (region == 0) ? g_qh : g_kh;
            #pragma unroll
            for (int nf = 0; nf < 8; nf++) {
                int d = nf * 8 + qk;
                float2 fA = fr2[lA * (D_ / 2) + (d >> 1)];
                float2 fB = fr2[lB * (D_ / 2) + (d >> 1)];
                float reA = acc[mf][nf][0] * invA, imA = acc[mf][nf][1] * invA;
                float reB = acc[mf][nf][2] * invB, imB = acc[mf][nf][3] * invB;
                *(uint32_t*)(dst + baseA + d) =
                    pack_f16(reA * fA.x - imA * fA.y, reA * fA.y + imA * fA.x);
                *(uint32_t*)(dst + baseB + d) =
                    pack_f16(reB * fB.x - imB * fB.y, reB * fB.y + imB * fB.x);
            }
        } else {
            #pragma unroll
            for (int nf = 0; nf < 8; nf++) {
                int d = nf * 8 + qk;
                *(uint32_t*)(g_vh + baseA + d) = pack_f16(acc[mf][nf][0], acc[mf][nf][1]);
                *(uint32_t*)(g_vh + baseB + d) = pack_f16(acc[mf][nf][2], acc[mf][nf][3]);
            }
        }
    }
}

// ---------------------------------------------------------------------------
// Proj GEMM: pure fp16 1-term. K-chunk 64, 3-stage cp.async.
// ---------------------------------------------------------------------------
__global__ __launch_bounds__(256, 2) void gemm_proj_kernel(
    const __half* __restrict__ Ahi, const __half* __restrict__ Bhi,
    float* __restrict__ Cm, const float* __restrict__ bias,
    int N, int K)
{
    extern __shared__ __align__(16) char smc[];
    uint32_t sb = smem_u32(smc);
    int t = threadIdx.x;
    int wid = t >> 5, lane = t & 31;
    int wm = wid & 3, wn = wid >> 2;
    int m0 = blockIdx.y * 128, n0 = blockIdx.x * 128;

    float acc[2][8][4];
    #pragma unroll
    for (int i = 0; i < 2; i++)
        #pragma unroll
        for (int j = 0; j < 8; j++)
            #pragma unroll
            for (int u = 0; u < 4; u++) acc[i][j][u] = 0.f;

    int qrow = lane >> 2;
    int qk   = (lane & 3) * 2;
    int g = lane >> 3, r8 = lane & 7;
    int arow = (g & 1) * 8 + r8;
    uint32_t xv = (uint32_t)(r8 << 4);
    uint32_t ccol = (uint32_t)((g >> 1) * 16);
    const int niter = K >> 6;

    auto issue = [&](int it, int s) {
        int k0 = it << 6;
        uint32_t stb = sb + (uint32_t)s * PSTAGE;
        #pragma unroll
        for (int i = 0; i < 4; i++) {
            int c = t + i * 256;
            int row = c >> 3, cg = c & 7;
            uint32_t off = (uint32_t)(row * 128 + cg * 16);
            uint32_t swo = off ^ ((off >> 3) & 0x70);
            cp_async16(stb + swo,
                       Ahi + (size_t)(m0 + row) * K + k0 + cg * 8);
            cp_async16(stb + 16384 + swo,
                       Bhi + (size_t)(n0 + row) * K + k0 + cg * 8);
        }
        cp_commit();
    };

    issue(0, 0);
    issue(1, 1);
    int s = 0;
    for (int it = 0; it < niter; it++) {
        if (it + 1 < niter) cp_wait<1>(); else cp_wait<0>();
        __syncthreads();
        if (it + 2 < niter) {
            int s2 = s + 2; if (s2 >= 3) s2 -= 3;
            issue(it + 2, s2);
        }

        uint32_t sA = sb + (uint32_t)s * PSTAGE;
        uint32_t sB = sA + 16384;

        #pragma unroll
        for (int ks = 0; ks < 4; ks++) {
            uint32_t cc = ((uint32_t)(ks * 32) + ccol) ^ xv;
            uint32_t afh[2][4];
            #pragma unroll
            for (int mf = 0; mf < 2; mf++) {
                uint32_t rb = (uint32_t)((wm * 32 + mf * 16 + arow) * 128);
                ldsm_x4(afh[mf], sA + rb + cc);
            }
            #pragma unroll
            for (int nfp = 0; nfp < 4; nfp++) {
                uint32_t rb = (uint32_t)((wn * 64 + nfp * 16 + arow) * 128);
                uint32_t b4[4];
                ldsm_x4(b4, sB + rb + cc);
                #pragma unroll
                for (int mf = 0; mf < 2; mf++) {
                    mma16816(acc[mf][2 * nfp],     afh[mf], b4[0], b4[2]);
                    mma16816(acc[mf][2 * nfp + 1], afh[mf], b4[1], b4[3]);
                }
            }
        }
        if (++s >= 3) s -= 3;
    }

    #pragma unroll
    for (int mf = 0; mf < 2; mf++) {
        #pragma unroll
        for (int nf = 0; nf < 8; nf++) {
            int row = m0 + wm * 32 + mf * 16 + qrow;
            int col = n0 + wn * 64 + nf * 8 + qk;
            float bv0 = bias[col];
            float bv1 = bias[col + 1];
            *(float2*)(Cm + (size_t)row * N + col) =
                make_float2(acc[mf][nf][0] + bv0, acc[mf][nf][1] + bv1);
            *(float2*)(Cm + (size_t)(row + 8) * N + col) =
                make_float2(acc[mf][nf][2] + bv0, acc[mf][nf][3] + bv1);
        }
    }
}

// ---------------------------------------------------------------------------
// Flash attention, pure fp16 HMMA. 128-query CTA (8 warps, 256 threads),
// 3-stage cp.async on 64-key K/V tiles.
// ---------------------------------------------------------------------------
#define ASTAGE 16384
__global__ __launch_bounds__(256) void attn_mma_kernel(
    const float* __restrict__ bias)
{
    extern __shared__ __align__(16) char asmem[];
    uint32_t sbase = smem_u32(asmem);

    int t = threadIdx.x;
    int wid = t >> 5, lane = t & 31;
    int q0 = blockIdx.x * 128;
    int bh = blockIdx.y;
    int b = bh >> 4, h = bh & 15;

    const __half* Qh = g_qh + (size_t)bh * L_ * D_;
    const __half* Kh = g_kh + (size_t)bh * L_ * D_;
    const __half* Vh = g_vh + (size_t)bh * L_ * D_;

    int rA = q0 + wid * 16 + (lane >> 2);
    int c0 = (lane & 3) * 2;

    uint32_t qa_h[4][4];
    #pragma unroll
    for (int kf = 0; kf < 4; kf++) {
        int cb = kf * 16 + c0;
        qa_h[kf][0] = *(const uint32_t*)(Qh + (size_t)rA * D_ + cb);
        qa_h[kf][1] = *(const uint32_t*)(Qh + (size_t)(rA + 8) * D_ + cb);
        qa_h[kf][2] = *(const uint32_t*)(Qh + (size_t)rA * D_ + cb + 8);
        qa_h[kf][3] = *(const uint32_t*)(Qh + (size_t)(rA + 8) * D_ + cb + 8);
    }

    float m0 = -CUDART_INF_F, m1 = -CUDART_INF_F;
    float l0 = 0.f, l1 = 0.f;
    float oacc[8][4];
    #pragma unroll
    for (int nf = 0; nf < 8; nf++)
        #pragma unroll
        for (int u = 0; u < 4; u++) oacc[nf][u] = 0.f;

    int g = lane >> 3, r8 = lane & 7;
    uint32_t xv = (uint32_t)(r8 << 4);
    uint32_t krow = (uint32_t)((g >> 1) * 8 + r8);
    uint32_t kcol = (uint32_t)((g & 1) * 16);
    uint32_t vrow = (uint32_t)((g & 1) * 8 + r8);
    uint32_t vcol = (uint32_t)((g >> 1) * 16);

    const float* brow0 = bias + (size_t)rA * L_;
    const float* brow1 = bias + (size_t)(rA + 8) * L_;

    auto issue_kv = [&](int k0, int s) {
        uint32_t stb = sbase + (uint32_t)s * ASTAGE;
        #pragma unroll
        for (int i = 0; i < 2; i++) {
            int c = t + i * 256;
            int row = c >> 3, cg = c & 7;
            uint32_t off = (uint32_t)(row * 128 + cg * 16);
            uint32_t swo = off ^ ((off >> 3) & 0x70);
            size_t gsrc = (size_t)(k0 + row) * D_ + cg * 8;
            cp_async16(stb + swo,        Kh + gsrc);
            cp_async16(stb + 8192 + swo, Vh + gsrc);
        }
        cp_commit();
    };

    issue_kv(0, 0);
    issue_kv(64, 1);
    const int NIT = L_ / 64;
    int s = 0;
    for (int ki = 0; ki < NIT; ki++) {
        if (ki + 1 < NIT) cp_wait<1>(); else cp_wait<0>();
        __syncthreads();
        if (ki + 2 < NIT) {
            int s2 = s + 2; if (s2 >= 3) s2 -= 3;
            issue_kv((ki + 2) * 64, s2);
        }

        uint32_t sk = sbase + (uint32_t)s * ASTAGE;
        uint32_t sv = sk + 8192;
        int k0 = ki * 64;

        float sacc[8][4];
        #pragma unroll
        for (int nf = 0; nf < 8; nf++)
            #pragma unroll
            for (int u = 0; u < 4; u++) sacc[nf][u] = 0.f;

        #pragma unroll
        for (int nfp = 0; nfp < 4; nfp++) {
            #pragma unroll
            for (int kf = 0; kf < 4; kf++) {
                uint32_t addr = sk + (uint32_t)((nfp * 16 + krow) * 128)
                              + (((uint32_t)(kf * 32) + kcol) ^ xv);
                uint32_t kb4[4];
                ldsm_x4(kb4, addr);
                mma16816(sacc[2 * nfp],     qa_h[kf], kb4[0], kb4[1]);
                mma16816(sacc[2 * nfp + 1], qa_h[kf], kb4[2], kb4[3]);
            }
        }

        #pragma unroll
        for (int nf = 0; nf < 8; nf++) {
            int kc = k0 + nf * 8 + c0;
            float2 b0 = *(const float2*)(brow0 + kc);
            float2 b1 = *(const float2*)(brow1 + kc);
            sacc[nf][0] += b0.x; sacc[nf][1] += b0.y;
            sacc[nf][2] += b1.x; sacc[nf][3] += b1.y;
        }

        float mx0 = -CUDART_INF_F, mx1 = -CUDART_INF_F;
        #pragma unroll
        for (int nf = 0; nf < 8; nf++) {
            mx0 = fmaxf(mx0, fmaxf(sacc[nf][0], sacc[nf][1]));
            mx1 = fmaxf(mx1, fmaxf(sacc[nf][2], sacc[nf][3]));
        }
        mx0 = fmaxf(mx0, __shfl_xor_sync(0xffffffffu, mx0, 1));
        mx0 = fmaxf(mx0, __shfl_xor_sync(0xffffffffu, mx0, 2));
        mx1 = fmaxf(mx1, __shfl_xor_sync(0xffffffffu, mx1, 1));
        mx1 = fmaxf(mx1, __shfl_xor_sync(0xffffffffu, mx1, 2));

        float mn0 = fmaxf(m0, mx0), mn1 = fmaxf(m1, mx1);
        float cr0 = __expf(m0 - mn0), cr1 = __expf(m1 - mn1);
        float rs0 = 0.f, rs1 = 0.f;
        #pragma unroll
        for (int nf = 0; nf < 8; nf++) {
            sacc[nf][0] = __expf(sacc[nf][0] - mn0);
            sacc[nf][1] = __expf(sacc[nf][1] - mn0);
            sacc[nf][2] = __expf(sacc[nf][2] - mn1);
            sacc[nf][3] = __expf(sacc[nf][3] - mn1);
            rs0 += sacc[nf][0] + sacc[nf][1];
            rs1 += sacc[nf][2] + sacc[nf][3];
        }
        rs0 += __shfl_xor_sync(0xffffffffu, rs0, 1);
        rs0 += __shfl_xor_sync(0xffffffffu, rs0, 2);
        rs1 += __shfl_xor_sync(0xffffffffu, rs1, 1);
        rs1 += __shfl_xor_sync(0xffffffffu, rs1, 2);
        l0 = l0 * cr0 + rs0;
        l1 = l1 * cr1 + rs1;
        m0 = mn0; m1 = mn1;

        #pragma unroll
        for (int nf = 0; nf < 8; nf++) {
            oacc[nf][0] *= cr0; oacc[nf][1] *= cr0;
            oacc[nf][2] *= cr1; oacc[nf][3] *= cr1;
        }

        uint32_t pa_h[4][4];
        #pragma unroll
        for (int kf = 0; kf < 4; kf++) {
            #pragma unroll
            for (int half = 0; half < 2; half++) {
                int nf = 2 * kf + half;
                pa_h[kf][2 * half]     = pack_f16(sacc[nf][0], sacc[nf][1]);
                pa_h[kf][2 * half + 1] = pack_f16(sacc[nf][2], sacc[nf][3]);
            }
        }

        #pragma unroll
        for (int nfp = 0; nfp < 4; nfp++) {
            #pragma unroll
            for (int kf = 0; kf < 4; kf++) {
                uint32_t addr = sv + (uint32_t)((kf * 16 + vrow) * 128)
                              + (((uint32_t)(nfp * 32) + vcol) ^ xv);
                uint32_t vb4[4];
                ldsm_x4_t(vb4, addr);
                mma16816(oacc[2 * nfp],     pa_h[kf], vb4[0], vb4[1]);
                mma16816(oacc[2 * nfp + 1], pa_h[kf], vb4[2], vb4[3]);
            }
        }
        if (++s >= 3) s -= 3;
    }

    float inv0 = 1.f / l0, inv1 = 1.f / l1;
    size_t orow0 = (size_t)(b * L_ + rA) * C_ + h * D_;
    size_t orow1 = (size_t)(b * L_ + rA + 8) * C_ + h * D_;
    #pragma unroll
    for (int nf = 0; nf < 8; nf++) {
        int d = nf * 8 + c0;
        *(uint32_t*)(g_aoh + orow0 + d) = pack_f16(oacc[nf][0] * inv0, oacc[nf][1] * inv0);
        *(uint32_t*)(g_aoh + orow1 + d) = pack_f16(oacc[nf][2] * inv1, oacc[nf][3] * inv1);
    }
}

// ---------------------------------------------------------------------------
extern "C" void kernel_launch(void* const* d_in, const int* in_sizes, int n_in,
                              void* d_out, int out_size)
{
    const float* x         = (const float*)d_in[0];
    const float* freqs     = (const float*)d_in[1];
    const float* attn_bias = (const float*)d_in[2];
    const float* W_qkv     = (const float*)d_in[3];
    const float* q_bias    = (const float*)d_in[4];
    const float* v_bias    = (const float*)d_in[5];
    const float* sml       = (const float*)d_in[6];
    const float* W_proj    = (const float*)d_in[7];
    const float* b_proj    = (const float*)d_in[8];
    float* out = (float*)d_out;

    void* p;
    cudaGetSymbolAddress(&p, g_xhi); __half* xhi = (__half*)p;
    cudaGetSymbolAddress(&p, g_wqh); __half* wqh = (__half*)p;
    cudaGetSymbolAddress(&p, g_wph); __half* wph = (__half*)p;
    cudaGetSymbolAddress(&p, g_aoh); __half* aoh = (__half*)p;

    int psm = 3 * PSTAGE;      // 98304
    int asm_ = 3 * ASTAGE;     // 49152
    static bool attr_set = false;
    if (!attr_set) {
        cudaFuncSetAttribute(gemm_qkv_kernel,
                             cudaFuncAttributeMaxDynamicSharedMemorySize, psm);
        cudaFuncSetAttribute(gemm_proj_kernel,
                             cudaFuncAttributeMaxDynamicSharedMemorySize, psm);
        cudaFuncSetAttribute(attn_mma_kernel,
                             cudaFuncAttributeMaxDynamicSharedMemorySize, asm_);
        attr_set = true;
    }

    int ntot = N4X + N4WQ + N4WP;
    conv_all_kernel<<<(ntot + 255) / 256, 256>>>(x, W_qkv, W_proj, xhi, wqh, wph);

    gemm_qkv_kernel<<<dim3(3 * C_ / 128, B_ * L_ / 128), 256, psm>>>(
        xhi, wqh, q_bias, v_bias, freqs, sml, 3 * C_, C_);

    attn_mma_kernel<<<dim3(L_ / 128, B_ * H_), 256, asm_>>>(attn_bias);

    gemm_proj_kernel<<<dim3(C_ / 128, B_ * L_ / 128), 256, psm>>>(
        aoh, wph, out, b_proj, C_, C_);
}

// round 17
// speedup vs baseline: 1.1569x; 1.1569x over previous
#include <cuda_runtime.h>
#include <cuda_fp16.h>
#include <math_constants.h>
#include <cstdint>
#include <cstddef>

#define B_ 8
#define L_ 1024
#define C_ 1024
#define H_ 16
#define D_ 64
#define MAXSC 4.6051701859880914f  // log(100)

// ---------------------------------------------------------------------------
// Scratch (bss, no runtime allocation)
// ---------------------------------------------------------------------------
__device__ __half g_xhi[B_ * L_ * C_];
__device__ __half g_wqh[3 * C_ * C_];
__device__ __half g_wph[C_ * C_];

__device__ __half g_qh[B_ * H_ * L_ * D_];
__device__ __half g_kh[B_ * H_ * L_ * D_];
__device__ __half g_vh[B_ * H_ * L_ * D_];

__device__ __half g_aoh[B_ * L_ * C_];
__device__ int g_bias_nz;

// ---------------------------------------------------------------------------
// Helpers
// ---------------------------------------------------------------------------
__device__ __forceinline__ uint32_t smem_u32(const void* p) {
    uint32_t a;
    asm("{ .reg .u64 t; cvta.to.shared.u64 t, %1; cvt.u32.u64 %0, t; }"
        : "=r"(a) : "l"(p));
    return a;
}

__device__ __forceinline__ void mma16816(float* c, const uint32_t* a,
                                         uint32_t b0, uint32_t b1)
{
    asm volatile(
        "mma.sync.aligned.m16n8k16.row.col.f32.f16.f16.f32 "
        "{%0,%1,%2,%3}, {%4,%5,%6,%7}, {%8,%9}, {%0,%1,%2,%3};"
        : "+f"(c[0]), "+f"(c[1]), "+f"(c[2]), "+f"(c[3])
        : "r"(a[0]), "r"(a[1]), "r"(a[2]), "r"(a[3]), "r"(b0), "r"(b1));
}

__device__ __forceinline__ void ldsm_x4(uint32_t* r, uint32_t addr) {
    asm volatile("ldmatrix.sync.aligned.m8n8.x4.shared.b16 {%0,%1,%2,%3}, [%4];"
        : "=r"(r[0]), "=r"(r[1]), "=r"(r[2]), "=r"(r[3]) : "r"(addr));
}
__device__ __forceinline__ void ldsm_x4_t(uint32_t* r, uint32_t addr) {
    asm volatile("ldmatrix.sync.aligned.m8n8.x4.trans.shared.b16 {%0,%1,%2,%3}, [%4];"
        : "=r"(r[0]), "=r"(r[1]), "=r"(r[2]), "=r"(r[3]) : "r"(addr));
}

__device__ __forceinline__ uint32_t pack_f16(float a, float b) {
    __half2 t = __floats2half2_rn(a, b);
    return *(uint32_t*)&t;
}

__device__ __forceinline__ void cp_async16(uint32_t saddr, const void* gptr) {
    asm volatile("cp.async.cg.shared.global [%0], [%1], 16;"
        :: "r"(saddr), "l"(gptr) : "memory");
}
__device__ __forceinline__ void cp_commit() {
    asm volatile("cp.async.commit_group;" ::: "memory");
}
template <int N>
__device__ __forceinline__ void cp_wait() {
    asm volatile("cp.async.wait_group %0;" :: "n"(N) : "memory");
}

// ---------------------------------------------------------------------------
// Merged fp32->fp16 conversion for x, W_qkv, W_proj + bias zero-check
// ---------------------------------------------------------------------------
#define N4X  (B_ * L_ * C_ / 4)
#define N4WQ (3 * C_ * C_ / 4)
#define N4WP (C_ * C_ / 4)
#define N4B  (L_ * L_ / 4)
__global__ __launch_bounds__(256) void conv_all_kernel(
    const float* __restrict__ x, const float* __restrict__ wq,
    const float* __restrict__ wp, const float* __restrict__ bias,
    __half* __restrict__ xhi, __half* __restrict__ wqh,
    __half* __restrict__ wph)
{
    int i = blockIdx.x * blockDim.x + threadIdx.x;
    const float* src;
    __half* dst;
    int j;
    if (i < N4X) { src = x; dst = xhi; j = i; }
    else if (i < N4X + N4WQ) { src = wq; dst = wqh; j = i - N4X; }
    else if (i < N4X + N4WQ + N4WP) { src = wp; dst = wph; j = i - N4X - N4WQ; }
    else if (i < N4X + N4WQ + N4WP + N4B) {
        j = i - N4X - N4WQ - N4WP;
        float4 v = ((const float4*)bias)[j];
        if (v.x != 0.f || v.y != 0.f || v.z != 0.f || v.w != 0.f)
            atomicOr(&g_bias_nz, 1);
        return;
    }
    else return;
    float4 v = ((const float4*)src)[j];
    ((__half2*)dst)[2 * j]     = __floats2half2_rn(v.x, v.y);
    ((__half2*)dst)[2 * j + 1] = __floats2half2_rn(v.z, v.w);
}

// ---------------------------------------------------------------------------
// QKV GEMM: pure fp16 1-term.  K-chunk 64, 2-stage cp.async.
// Fused epilogue: l2norm + scale + RoPE -> g_qh/kh/vh.
// ---------------------------------------------------------------------------
#define PSTAGE 32768
__global__ __launch_bounds__(256, 2) void gemm_qkv_kernel(
    const __half* __restrict__ Ahi, const __half* __restrict__ Bhi,
    const float* __restrict__ bias_q, const float* __restrict__ bias_v,
    const float* __restrict__ freqs, const float* __restrict__ sml,
    int N, int K)
{
    extern __shared__ __align__(16) char smc[];
    uint32_t sb = smem_u32(smc);
    int t = threadIdx.x;
    int wid = t >> 5, lane = t & 31;
    int wm = wid & 3, wn = wid >> 2;
    int m0 = blockIdx.y * 128, n0 = blockIdx.x * 128;

    float acc[2][8][4];
    #pragma unroll
    for (int i = 0; i < 2; i++)
        #pragma unroll
        for (int j = 0; j < 8; j++)
            #pragma unroll
            for (int u = 0; u < 4; u++) acc[i][j][u] = 0.f;

    int qrow = lane >> 2;
    int qk   = (lane & 3) * 2;
    int g = lane >> 3, r8 = lane & 7;
    int arow = (g & 1) * 8 + r8;
    uint32_t xv = (uint32_t)(r8 << 4);
    uint32_t ccol = (uint32_t)((g >> 1) * 16);
    const int niter = K >> 6;

    auto issue = [&](int it, int s) {
        int k0 = it << 6;
        uint32_t stb = sb + (uint32_t)s * PSTAGE;
        #pragma unroll
        for (int i = 0; i < 4; i++) {
            int c = t + i * 256;
            int row = c >> 3, cg = c & 7;
            uint32_t off = (uint32_t)(row * 128 + cg * 16);
            uint32_t swo = off ^ ((off >> 3) & 0x70);
            cp_async16(stb + swo,
                       Ahi + (size_t)(m0 + row) * K + k0 + cg * 8);
            cp_async16(stb + 16384 + swo,
                       Bhi + (size_t)(n0 + row) * K + k0 + cg * 8);
        }
        cp_commit();
    };

    issue(0, 0);
    for (int it = 0; it < niter; it++) {
        int s = it & 1;
        cp_wait<0>();
        __syncthreads();
        if (it + 1 < niter) issue(it + 1, s ^ 1);

        uint32_t sA = sb + (uint32_t)s * PSTAGE;
        uint32_t sB = sA + 16384;

        #pragma unroll
        for (int ks = 0; ks < 4; ks++) {
            uint32_t cc = ((uint32_t)(ks * 32) + ccol) ^ xv;
            uint32_t afh[2][4];
            #pragma unroll
            for (int mf = 0; mf < 2; mf++) {
                uint32_t rb = (uint32_t)((wm * 32 + mf * 16 + arow) * 128);
                ldsm_x4(afh[mf], sA + rb + cc);
            }
            #pragma unroll
            for (int nfp = 0; nfp < 4; nfp++) {
                uint32_t rb = (uint32_t)((wn * 64 + nfp * 16 + arow) * 128);
                uint32_t b4[4];
                ldsm_x4(b4, sB + rb + cc);
                #pragma unroll
                for (int mf = 0; mf < 2; mf++) {
                    mma16816(acc[mf][2 * nfp],     afh[mf], b4[0], b4[2]);
                    mma16816(acc[mf][2 * nfp + 1], afh[mf], b4[1], b4[3]);
                }
            }
        }
    }

    // fused l2norm + scale + RoPE epilogue.  region 0=q, 1=k, 2=v.
    int region = blockIdx.x >> 3;
    int head   = ((blockIdx.x & 7) << 1) + wn;
    float smul = (region == 0) ? __expf(fminf(sml[head], MAXSC)) : 1.f;
    const float2* fr2 = (const float2*)freqs;

    #pragma unroll
    for (int mf = 0; mf < 2; mf++) {
        int r0 = m0 + wm * 32 + mf * 16 + qrow;
        int bb = r0 >> 10;
        int lA = r0 & 1023, lB = lA + 8;
        size_t baseA = ((size_t)(bb * H_ + head) * L_ + lA) * D_;
        size_t baseB = baseA + 8 * D_;

        float sA = 0.f, sB = 0.f;
        #pragma unroll
        for (int nf = 0; nf < 8; nf++) {
            int d = nf * 8 + qk;
            float bv0 = 0.f, bv1 = 0.f;
            if (region == 0) { bv0 = bias_q[head * D_ + d]; bv1 = bias_q[head * D_ + d + 1]; }
            if (region == 2) { bv0 = bias_v[head * D_ + d]; bv1 = bias_v[head * D_ + d + 1]; }
            acc[mf][nf][0] += bv0; acc[mf][nf][1] += bv1;
            acc[mf][nf][2] += bv0; acc[mf][nf][3] += bv1;
            if (region < 2) {
                sA += acc[mf][nf][0] * acc[mf][nf][0] + acc[mf][nf][1] * acc[mf][nf][1];
                sB += acc[mf][nf][2] * acc[mf][nf][2] + acc[mf][nf][3] * acc[mf][nf][3];
            }
        }

        if (region < 2) {
            sA += __shfl_xor_sync(0xffffffffu, sA, 1);
            sA += __shfl_xor_sync(0xffffffffu, sA, 2);
            sB += __shfl_xor_sync(0xffffffffu, sB, 1);
            sB += __shfl_xor_sync(0xffffffffu, sB, 2);
            float invA = smul / fmaxf(sqrtf(sA), 1e-12f);
            float invB = smul / fmaxf(sqrtf(sB), 1e-12f);

            __half* dst = (region == 0) ? g_qh : g_kh;
            #pragma unroll
            for (int nf = 0; nf < 8; nf++) {
                int d = nf * 8 + qk;
                float2 fA = fr2[lA * (D_ / 2) + (d >> 1)];
                float2 fB = fr2[lB * (D_ / 2) + (d >> 1)];
                float reA = acc[mf][nf][0] * invA, imA = acc[mf][nf][1] * invA;
                float reB = acc[mf][nf][2] * invB, imB = acc[mf][nf][3] * invB;
                *(uint32_t*)(dst + baseA + d) =
                    pack_f16(reA * fA.x - imA * fA.y, reA * fA.y + imA * fA.x);
                *(uint32_t*)(dst + baseB + d) =
                    pack_f16(reB * fB.x - imB * fB.y, reB * fB.y + imB * fB.x);
            }
        } else {
            #pragma unroll
            for (int nf = 0; nf < 8; nf++) {
                int d = nf * 8 + qk;
                *(uint32_t*)(g_vh + baseA + d) = pack_f16(acc[mf][nf][0], acc[mf][nf][1]);
                *(uint32_t*)(g_vh + baseB + d) = pack_f16(acc[mf][nf][2], acc[mf][nf][3]);
            }
        }
    }
}

// ---------------------------------------------------------------------------
// Proj GEMM: pure fp16 1-term. K-chunk 64, 2-stage cp.async.
// ---------------------------------------------------------------------------
__global__ __launch_bounds__(256, 2) void gemm_proj_kernel(
    const __half* __restrict__ Ahi, const __half* __restrict__ Bhi,
    float* __restrict__ Cm, const float* __restrict__ bias,
    int N, int K)
{
    extern __shared__ __align__(16) char smc[];
    uint32_t sb = smem_u32(smc);
    int t = threadIdx.x;
    int wid = t >> 5, lane = t & 31;
    int wm = wid & 3, wn = wid >> 2;
    int m0 = blockIdx.y * 128, n0 = blockIdx.x * 128;

    float acc[2][8][4];
    #pragma unroll
    for (int i = 0; i < 2; i++)
        #pragma unroll
        for (int j = 0; j < 8; j++)
            #pragma unroll
            for (int u = 0; u < 4; u++) acc[i][j][u] = 0.f;

    int qrow = lane >> 2;
    int qk   = (lane & 3) * 2;
    int g = lane >> 3, r8 = lane & 7;
    int arow = (g & 1) * 8 + r8;
    uint32_t xv = (uint32_t)(r8 << 4);
    uint32_t ccol = (uint32_t)((g >> 1) * 16);
    const int niter = K >> 6;

    auto issue = [&](int it, int s) {
        int k0 = it << 6;
        uint32_t stb = sb + (uint32_t)s * PSTAGE;
        #pragma unroll
        for (int i = 0; i < 4; i++) {
            int c = t + i * 256;
            int row = c >> 3, cg = c & 7;
            uint32_t off = (uint32_t)(row * 128 + cg * 16);
            uint32_t swo = off ^ ((off >> 3) & 0x70);
            cp_async16(stb + swo,
                       Ahi + (size_t)(m0 + row) * K + k0 + cg * 8);
            cp_async16(stb + 16384 + swo,
                       Bhi + (size_t)(n0 + row) * K + k0 + cg * 8);
        }
        cp_commit();
    };

    issue(0, 0);
    for (int it = 0; it < niter; it++) {
        int s = it & 1;
        cp_wait<0>();
        __syncthreads();
        if (it + 1 < niter) issue(it + 1, s ^ 1);

        uint32_t sA = sb + (uint32_t)s * PSTAGE;
        uint32_t sB = sA + 16384;

        #pragma unroll
        for (int ks = 0; ks < 4; ks++) {
            uint32_t cc = ((uint32_t)(ks * 32) + ccol) ^ xv;
            uint32_t afh[2][4];
            #pragma unroll
            for (int mf = 0; mf < 2; mf++) {
                uint32_t rb = (uint32_t)((wm * 32 + mf * 16 + arow) * 128);
                ldsm_x4(afh[mf], sA + rb + cc);
            }
            #pragma unroll
            for (int nfp = 0; nfp < 4; nfp++) {
                uint32_t rb = (uint32_t)((wn * 64 + nfp * 16 + arow) * 128);
                uint32_t b4[4];
                ldsm_x4(b4, sB + rb + cc);
                #pragma unroll
                for (int mf = 0; mf < 2; mf++) {
                    mma16816(acc[mf][2 * nfp],     afh[mf], b4[0], b4[2]);
                    mma16816(acc[mf][2 * nfp + 1], afh[mf], b4[1], b4[3]);
                }
            }
        }
    }

    #pragma unroll
    for (int mf = 0; mf < 2; mf++) {
        #pragma unroll
        for (int nf = 0; nf < 8; nf++) {
            int row = m0 + wm * 32 + mf * 16 + qrow;
            int col = n0 + wn * 64 + nf * 8 + qk;
            float bv0 = bias[col];
            float bv1 = bias[col + 1];
            *(float2*)(Cm + (size_t)row * N + col) =
                make_float2(acc[mf][nf][0] + bv0, acc[mf][nf][1] + bv1);
            *(float2*)(Cm + (size_t)(row + 8) * N + col) =
                make_float2(acc[mf][nf][2] + bv0, acc[mf][nf][3] + bv1);
        }
    }
}

// ---------------------------------------------------------------------------
// Flash attention, pure fp16 HMMA. 128-query CTA (8 warps, 256 threads),
// 3-stage cp.async on 64-key K/V tiles. Bias add skipped when bias==0.
// ---------------------------------------------------------------------------
#define ASTAGE 16384
__global__ __launch_bounds__(256) void attn_mma_kernel(
    const float* __restrict__ bias)
{
    extern __shared__ __align__(16) char asmem[];
    uint32_t sbase = smem_u32(asmem);

    int t = threadIdx.x;
    int wid = t >> 5, lane = t & 31;
    int q0 = blockIdx.x * 128;
    int bh = blockIdx.y;
    int b = bh >> 4, h = bh & 15;
    int bnz = g_bias_nz;

    const __half* Qh = g_qh + (size_t)bh * L_ * D_;
    const __half* Kh = g_kh + (size_t)bh * L_ * D_;
    const __half* Vh = g_vh + (size_t)bh * L_ * D_;

    int rA = q0 + wid * 16 + (lane >> 2);
    int c0 = (lane & 3) * 2;

    uint32_t qa_h[4][4];
    #pragma unroll
    for (int kf = 0; kf < 4; kf++) {
        int cb = kf * 16 + c0;
        qa_h[kf][0] = *(const uint32_t*)(Qh + (size_t)rA * D_ + cb);
        qa_h[kf][1] = *(const uint32_t*)(Qh + (size_t)(rA + 8) * D_ + cb);
        qa_h[kf][2] = *(const uint32_t*)(Qh + (size_t)rA * D_ + cb + 8);
        qa_h[kf][3] = *(const uint32_t*)(Qh + (size_t)(rA + 8) * D_ + cb + 8);
    }

    float m0 = -CUDART_INF_F, m1 = -CUDART_INF_F;
    float l0 = 0.f, l1 = 0.f;
    float oacc[8][4];
    #pragma unroll
    for (int nf = 0; nf < 8; nf++)
        #pragma unroll
        for (int u = 0; u < 4; u++) oacc[nf][u] = 0.f;

    int g = lane >> 3, r8 = lane & 7;
    uint32_t xv = (uint32_t)(r8 << 4);
    uint32_t krow = (uint32_t)((g >> 1) * 8 + r8);
    uint32_t kcol = (uint32_t)((g & 1) * 16);
    uint32_t vrow = (uint32_t)((g & 1) * 8 + r8);
    uint32_t vcol = (uint32_t)((g >> 1) * 16);

    const float* brow0 = bias + (size_t)rA * L_;
    const float* brow1 = bias + (size_t)(rA + 8) * L_;

    auto issue_kv = [&](int k0, int s) {
        uint32_t stb = sbase + (uint32_t)s * ASTAGE;
        #pragma unroll
        for (int i = 0; i < 2; i++) {
            int c = t + i * 256;
            int row = c >> 3, cg = c & 7;
            uint32_t off = (uint32_t)(row * 128 + cg * 16);
            uint32_t swo = off ^ ((off >> 3) & 0x70);
            size_t gsrc = (size_t)(k0 + row) * D_ + cg * 8;
            cp_async16(stb + swo,        Kh + gsrc);
            cp_async16(stb + 8192 + swo, Vh + gsrc);
        }
        cp_commit();
    };

    issue_kv(0, 0);
    issue_kv(64, 1);
    const int NIT = L_ / 64;
    int s = 0;
    for (int ki = 0; ki < NIT; ki++) {
        if (ki + 1 < NIT) cp_wait<1>(); else cp_wait<0>();
        __syncthreads();
        if (ki + 2 < NIT) {
            int s2 = s + 2; if (s2 >= 3) s2 -= 3;
            issue_kv((ki + 2) * 64, s2);
        }

        uint32_t sk = sbase + (uint32_t)s * ASTAGE;
        uint32_t sv = sk + 8192;
        int k0 = ki * 64;

        float sacc[8][4];
        #pragma unroll
        for (int nf = 0; nf < 8; nf++)
            #pragma unroll
            for (int u = 0; u < 4; u++) sacc[nf][u] = 0.f;

        #pragma unroll
        for (int nfp = 0; nfp < 4; nfp++) {
            #pragma unroll
            for (int kf = 0; kf < 4; kf++) {
                uint32_t addr = sk + (uint32_t)((nfp * 16 + krow) * 128)
                              + (((uint32_t)(kf * 32) + kcol) ^ xv);
                uint32_t kb4[4];
                ldsm_x4(kb4, addr);
                mma16816(sacc[2 * nfp],     qa_h[kf], kb4[0], kb4[1]);
                mma16816(sacc[2 * nfp + 1], qa_h[kf], kb4[2], kb4[3]);
            }
        }

        if (bnz) {
            #pragma unroll
            for (int nf = 0; nf < 8; nf++) {
                int kc = k0 + nf * 8 + c0;
                float2 b0 = *(const float2*)(brow0 + kc);
                float2 b1 = *(const float2*)(brow1 + kc);
                sacc[nf][0] += b0.x; sacc[nf][1] += b0.y;
                sacc[nf][2] += b1.x; sacc[nf][3] += b1.y;
            }
        }

        float mx0 = -CUDART_INF_F, mx1 = -CUDART_INF_F;
        #pragma unroll
        for (int nf = 0; nf < 8; nf++) {
            mx0 = fmaxf(mx0, fmaxf(sacc[nf][0], sacc[nf][1]));
            mx1 = fmaxf(mx1, fmaxf(sacc[nf][2], sacc[nf][3]));
        }
        mx0 = fmaxf(mx0, __shfl_xor_sync(0xffffffffu, mx0, 1));
        mx0 = fmaxf(mx0, __shfl_xor_sync(0xffffffffu, mx0, 2));
        mx1 = fmaxf(mx1, __shfl_xor_sync(0xffffffffu, mx1, 1));
        mx1 = fmaxf(mx1, __shfl_xor_sync(0xffffffffu, mx1, 2));

        float mn0 = fmaxf(m0, mx0), mn1 = fmaxf(m1, mx1);
        float cr0 = __expf(m0 - mn0), cr1 = __expf(m1 - mn1);
        float rs0 = 0.f, rs1 = 0.f;
        #pragma unroll
        for (int nf = 0; nf < 8; nf++) {
            sacc[nf][0] = __expf(sacc[nf][0] - mn0);
            sacc[nf][1] = __expf(sacc[nf][1] - mn0);
            sacc[nf][2] = __expf(sacc[nf][2] - mn1);
            sacc[nf][3] = __expf(sacc[nf][3] - mn1);
            rs0 += sacc[nf][0] + sacc[nf][1];
            rs1 += sacc[nf][2] + sacc[nf][3];
        }
        rs0 += __shfl_xor_sync(0xffffffffu, rs0, 1);
        rs0 += __shfl_xor_sync(0xffffffffu, rs0, 2);
        rs1 += __shfl_xor_sync(0xffffffffu, rs1, 1);
        rs1 += __shfl_xor_sync(0xffffffffu, rs1, 2);
        l0 = l0 * cr0 + rs0;
        l1 = l1 * cr1 + rs1;
        m0 = mn0; m1 = mn1;

        #pragma unroll
        for (int nf = 0; nf < 8; nf++) {
            oacc[nf][0] *= cr0; oacc[nf][1] *= cr0;
            oacc[nf][2] *= cr1; oacc[nf][3] *= cr1;
        }

        uint32_t pa_h[4][4];
        #pragma unroll
        for (int kf = 0; kf < 4; kf++) {
            #pragma unroll
            for (int half = 0; half < 2; half++) {
                int nf = 2 * kf + half;
                pa_h[kf][2 * half]     = pack_f16(sacc[nf][0], sacc[nf][1]);
                pa_h[kf][2 * half + 1] = pack_f16(sacc[nf][2], sacc[nf][3]);
            }
        }

        #pragma unroll
        for (int nfp = 0; nfp < 4; nfp++) {
            #pragma unroll
            for (int kf = 0; kf < 4; kf++) {
                uint32_t addr = sv + (uint32_t)((kf * 16 + vrow) * 128)
                              + (((uint32_t)(nfp * 32) + vcol) ^ xv);
                uint32_t vb4[4];
                ldsm_x4_t(vb4, addr);
                mma16816(oacc[2 * nfp],     pa_h[kf], vb4[0], vb4[1]);
                mma16816(oacc[2 * nfp + 1], pa_h[kf], vb4[2], vb4[3]);
            }
        }
        if (++s >= 3) s -= 3;
    }

    float inv0 = 1.f / l0, inv1 = 1.f / l1;
    size_t orow0 = (size_t)(b * L_ + rA) * C_ + h * D_;
    size_t orow1 = (size_t)(b * L_ + rA + 8) * C_ + h * D_;
    #pragma unroll
    for (int nf = 0; nf < 8; nf++) {
        int d = nf * 8 + c0;
        *(uint32_t*)(g_aoh + orow0 + d) = pack_f16(oacc[nf][0] * inv0, oacc[nf][1] * inv0);
        *(uint32_t*)(g_aoh + orow1 + d) = pack_f16(oacc[nf][2] * inv1, oacc[nf][3] * inv1);
    }
}

// ---------------------------------------------------------------------------
extern "C" void kernel_launch(void* const* d_in, const int* in_sizes, int n_in,
                              void* d_out, int out_size)
{
    const float* x         = (const float*)d_in[0];
    const float* freqs     = (const float*)d_in[1];
    const float* attn_bias = (const float*)d_in[2];
    const float* W_qkv     = (const float*)d_in[3];
    const float* q_bias    = (const float*)d_in[4];
    const float* v_bias    = (const float*)d_in[5];
    const float* sml       = (const float*)d_in[6];
    const float* W_proj    = (const float*)d_in[7];
    const float* b_proj    = (const float*)d_in[8];
    float* out = (float*)d_out;

    void* p;
    cudaGetSymbolAddress(&p, g_xhi); __half* xhi = (__half*)p;
    cudaGetSymbolAddress(&p, g_wqh); __half* wqh = (__half*)p;
    cudaGetSymbolAddress(&p, g_wph); __half* wph = (__half*)p;
    cudaGetSymbolAddress(&p, g_aoh); __half* aoh = (__half*)p;
    void* flagp;
    cudaGetSymbolAddress(&flagp, g_bias_nz);

    int psm = 2 * PSTAGE;      // 65536
    int asm_ = 3 * ASTAGE;     // 49152
    static bool attr_set = false;
    if (!attr_set) {
        cudaFuncSetAttribute(gemm_qkv_kernel,
                             cudaFuncAttributeMaxDynamicSharedMemorySize, psm);
        cudaFuncSetAttribute(gemm_proj_kernel,
                             cudaFuncAttributeMaxDynamicSharedMemorySize, psm);
        cudaFuncSetAttribute(attn_mma_kernel,
                             cudaFuncAttributeMaxDynamicSharedMemorySize, asm_);
        attr_set = true;
    }

    cudaMemsetAsync(flagp, 0, sizeof(int));

    int ntot = N4X + N4WQ + N4WP + N4B;
    conv_all_kernel<<<(ntot + 255) / 256, 256>>>(x, W_qkv, W_proj, attn_bias,
                                                 xhi, wqh, wph);

    gemm_qkv_kernel<<<dim3(3 * C_ / 128, B_ * L_ / 128), 256, psm>>>(
        xhi, wqh, q_bias, v_bias, freqs, sml, 3 * C_, C_);

    attn_mma_kernel<<<dim3(L_ / 128, B_ * H_), 256, asm_>>>(attn_bias);

    gemm_proj_kernel<<<dim3(C_ / 128, B_ * L_ / 128), 256, psm>>>(
        aoh, wph, out, b_proj, C_, C_);
}